// round 16
// baseline (speedup 1.0000x reference)
#include <cuda_runtime.h>
#include <cuda_fp16.h>
#include <cstdint>
#include <math.h>

#define B_SZ   2
#define SEQ    2048
#define DIM    1024
#define HEADS  16
#define HD     64
#define SCALE  0.125f
#define EXP_C  0.1803368801111243f   /* SCALE * log2(e) */
#define PBIAS  4.0f
#define M_TOTAL (B_SZ * SEQ)
#define QKV_N   (3 * DIM)
#define OUT_ELEMS  (B_SZ * SEQ * DIM)
#define BH      (B_SZ * HEADS)
#define PACKED_ELEMS (BH * SEQ * 128)
#define V_ELEMS      (BH * SEQ * HD)

// ---------------- scratch (static device globals, fp16, all plain) ----------------
__device__ __half g_xrh[OUT_ELEMS], g_xih[OUT_ELEMS];                  // x
__device__ __half g_wqr[QKV_N * DIM], g_wqi[QKV_N * DIM];              // Wqkv
__device__ __half g_wor[DIM * DIM], g_woi[DIM * DIM];                  // Wout
__device__ __half g_qph[PACKED_ELEMS];                                 // Q packed
__device__ __half g_kph[PACKED_ELEMS];                                 // K packed
__device__ __half g_vrh[V_ELEMS], g_vih[V_ELEMS];                      // V
__device__ __half g_oarh[OUT_ELEMS], g_oaih[OUT_ELEMS];                // O

// ---------------- helpers ----------------
__device__ __forceinline__ uint32_t smem_u32(const void* p) {
    uint32_t a;
    asm("{ .reg .u64 t; cvta.to.shared.u64 t, %1; cvt.u32.u64 %0, t; }" : "=r"(a) : "l"(p));
    return a;
}
__device__ __forceinline__ void cp_async16(uint32_t dst, const void* src) {
    asm volatile("cp.async.cg.shared.global [%0], [%1], 16;" :: "r"(dst), "l"(src) : "memory");
}
#define CP_COMMIT()  asm volatile("cp.async.commit_group;" ::: "memory")
#define CP_WAIT0()   asm volatile("cp.async.wait_group 0;" ::: "memory")
#define CP_WAIT1()   asm volatile("cp.async.wait_group 1;" ::: "memory")

__device__ __forceinline__ void mma_f16(float c[4], const uint32_t a[4], const uint32_t b[2]) {
    asm("mma.sync.aligned.m16n8k16.row.col.f32.f16.f16.f32 "
        "{%0,%1,%2,%3}, {%4,%5,%6,%7}, {%8,%9}, {%0,%1,%2,%3};"
        : "+f"(c[0]), "+f"(c[1]), "+f"(c[2]), "+f"(c[3])
        : "r"(a[0]), "r"(a[1]), "r"(a[2]), "r"(a[3]), "r"(b[0]), "r"(b[1]));
}
__device__ __forceinline__ void ldsm_x4(uint32_t r[4], uint32_t a) {
    asm volatile("ldmatrix.sync.aligned.m8n8.x4.shared.b16 {%0,%1,%2,%3}, [%4];"
                 : "=r"(r[0]), "=r"(r[1]), "=r"(r[2]), "=r"(r[3]) : "r"(a));
}
__device__ __forceinline__ void ldsm_x4t(uint32_t r[4], uint32_t a) {
    asm volatile("ldmatrix.sync.aligned.m8n8.x4.trans.shared.b16 {%0,%1,%2,%3}, [%4];"
                 : "=r"(r[0]), "=r"(r[1]), "=r"(r[2]), "=r"(r[3]) : "r"(a));
}
__device__ __forceinline__ uint32_t packh(float a, float b) {
    __half2 h = __floats2half2_rn(a, b);
    return *reinterpret_cast<uint32_t*>(&h);
}
__device__ __forceinline__ float ex2f(float x) {
    float r; asm("ex2.approx.f32 %0, %1;" : "=f"(r) : "f"(x)); return r;
}

// ---------------- fused fp32 -> fp16 conversions ----------------
#define N_X4   1048576
#define N_WQ4  786432
#define N_WO4  262144
#define SPLIT_TOTAL (2 * N_X4 + 2 * N_WQ4 + 2 * N_WO4)

__global__ void split_all(const float* __restrict__ x_r, const float* __restrict__ x_i,
                          const float* __restrict__ wq_r, const float* __restrict__ wq_i,
                          const float* __restrict__ wo_r, const float* __restrict__ wo_i)
{
    for (int i = blockIdx.x * blockDim.x + threadIdx.x; i < SPLIT_TOTAL;
         i += gridDim.x * blockDim.x) {
        const float* src; __half* dst; int off;
        if (i < 2 * N_X4) {
            if (i < N_X4) { src = x_r; dst = g_xrh; off = i; }
            else          { src = x_i; dst = g_xih; off = i - N_X4; }
        } else if (i < 2 * N_X4 + 2 * N_WQ4) {
            const int k = i - 2 * N_X4;
            if (k < N_WQ4) { src = wq_r; dst = g_wqr; off = k; }
            else           { src = wq_i; dst = g_wqi; off = k - N_WQ4; }
        } else {
            const int k = i - 2 * N_X4 - 2 * N_WQ4;
            if (k < N_WO4) { src = wo_r; dst = g_wor; off = k; }
            else           { src = wo_i; dst = g_woi; off = k - N_WO4; }
        }
        float4 v = ((const float4*)src)[off];
        uint2 hp;
        hp.x = packh(v.x, v.y); hp.y = packh(v.z, v.w);
        ((uint2*)dst)[off] = hp;
    }
}

// ============================================================
// HMMA plain-fp16 GEMM: D = A @ B^T + bias.
// 128 threads, 4 warps (2x2), warp tile 64x64 (attention-proven
// shape). K-chunk 64, 2-stage cp.async, pitch 144 B, 2 CTA/SM.
// Accumulation order per acc is unchanged -> bit-identical.
// ============================================================
#define TILE_G 18432                   /* 128 rows x 144 B */
#define STG_B  (2 * TILE_G)            /* A, B             */
#define GEMM_SMEM (2 * STG_B)          /* 73728            */
#define NCHUNK 16

template<int QKV>
__global__ __launch_bounds__(128, 2)
void gemm_f16(const float* __restrict__ bias_r, const float* __restrict__ bias_i,
              float* __restrict__ Yr, float* __restrict__ Yi)
{
    extern __shared__ char smc[];
    const uint32_t sb = smem_u32(smc);
    const int tid = threadIdx.x;
    const int wid = tid >> 5, lid = tid & 31;
    const int wm = wid >> 1, wn = wid & 1;       // 2 x 2 warp grid
    const int g = lid >> 2, tig = lid & 3;
    const int n0 = blockIdx.x * 128;
    const int m0 = blockIdx.y * 128;
    const int z  = blockIdx.z;

    const __half *A, *B;
    const float* bias;
    if (QKV) {
        if (z == 0) { A = g_xrh;  B = g_wqr; bias = bias_r; }
        else        { A = g_xih;  B = g_wqi; bias = bias_i; }
    } else {
        if (z == 0) { A = g_oarh; B = g_wor; bias = bias_r; }
        else        { A = g_oaih; B = g_woi; bias = bias_i; }
    }
    float* Y = (z == 0) ? Yr : Yi;

    auto issue_cp = [&](int chunk, int s) {
        const int k0 = chunk * 64;
        const uint32_t base = sb + (uint32_t)s * STG_B;
#pragma unroll
        for (int i = 0; i < 16; ++i) {
            const int lin = tid + i * 128;           // 0..2047
            const int t   = lin >> 10;               // 0=A, 1=B
            const int rc  = lin & 1023;
            const int row = rc >> 3, c = rc & 7;
            cp_async16(base + t * TILE_G + row * 144 + c * 16,
                       (t ? B : A) + (size_t)((t ? n0 : m0) + row) * DIM + k0 + c * 8);
        }
    };

    const uint32_t a_rel = (uint32_t)((wm * 64 + (lid & 15)) * 144 + ((lid >> 4) << 4));
    const uint32_t b_rel = (uint32_t)((wn * 64 + (lid & 7) + ((lid & 16) >> 1)) * 144 +
                                      ((lid & 8) << 1));

    float acc[4][8][4];
#pragma unroll
    for (int a = 0; a < 4; a++)
#pragma unroll
        for (int b = 0; b < 8; b++)
#pragma unroll
            for (int c = 0; c < 4; c++) acc[a][b][c] = 0.f;

    issue_cp(0, 0); CP_COMMIT();

    for (int j = 0; j < NCHUNK; ++j) {
        CP_WAIT0();
        __syncthreads();                 // chunk j visible; other stage free
        if (j + 1 < NCHUNK) { issue_cp(j + 1, (j + 1) & 1); CP_COMMIT(); }

        const uint32_t st = sb + (uint32_t)(j & 1) * STG_B;
        const uint32_t aA = st + a_rel;
        const uint32_t aB = st + TILE_G + b_rel;

#pragma unroll
        for (int ks = 0; ks < 4; ++ks) {
            uint32_t bf[4][4];
#pragma unroll
            for (int nb2 = 0; nb2 < 4; ++nb2)
                ldsm_x4(bf[nb2], aB + nb2 * (16 * 144) + ks * 32);
#pragma unroll
            for (int mi = 0; mi < 4; ++mi) {
                uint32_t ah[4];
                ldsm_x4(ah, aA + mi * (16 * 144) + ks * 32);
#pragma unroll
                for (int nb2 = 0; nb2 < 4; ++nb2) {
                    mma_f16(acc[mi][2 * nb2],     ah, bf[nb2]);
                    mma_f16(acc[mi][2 * nb2 + 1], ah, bf[nb2] + 2);
                }
            }
        }
    }

    // ---- epilogue ----
#pragma unroll
    for (int nb = 0; nb < 8; ++nb) {
        const int n = n0 + wn * 64 + nb * 8 + tig * 2;
        const float b0v = bias[n], b1v = bias[n + 1];
#pragma unroll
        for (int mi = 0; mi < 4; ++mi) {
            const int mlo = m0 + wm * 64 + mi * 16 + g;
#pragma unroll
            for (int half = 0; half < 2; ++half) {
                const int m = mlo + half * 8;
                const float y0 = acc[mi][nb][half * 2 + 0] + b0v;
                const float y1 = acc[mi][nb][half * 2 + 1] + b1v;
                if (!QKV) {
                    *(float2*)&Y[(size_t)m * DIM + n] = make_float2(y0, y1);
                } else {
                    const int which = n >> 10;
                    const int h = (n >> 6) & 15;
                    const int d = n & 63;
                    const int bh = (m >> 11) * HEADS + h;
                    const int ns = m & 2047;
                    const uint32_t hp = packh(y0, y1);
                    if (which == 2) {
                        const size_t idx = ((size_t)bh * SEQ + ns) * HD + d;
                        if (z == 0) *(uint32_t*)&g_vrh[idx] = hp;
                        else        *(uint32_t*)&g_vih[idx] = hp;
                    } else {
                        const size_t idx = ((size_t)bh * SEQ + ns) * 128 + d + (z ? 64 : 0);
                        if (which == 0) *(uint32_t*)&g_qph[idx] = hp;
                        else            *(uint32_t*)&g_kph[idx] = hp;
                    }
                }
            }
        }
    }
}

// ============================================================
// HMMA flash complex attention (unchanged from Round 15).
// ============================================================
#define NT 32
#define QSM   0u
#define KSM   17408u
#define VSM(b) (34816u + (uint32_t)(b) * 9216u)
#define ATT_SMEM 53248

__global__ __launch_bounds__(128, 2)
void attn_mma()
{
    extern __shared__ char smb[];
    const uint32_t sb = smem_u32(smb);
    const int tid = threadIdx.x, w = tid >> 5, L = tid & 31;
    const int bh = blockIdx.y, qt = blockIdx.x;
    const size_t kvrow0 = (size_t)bh * SEQ;

    auto issueQ = [&]() {
        const size_t qb = (kvrow0 + (size_t)qt * 64) * 128;
#pragma unroll
        for (int i = 0; i < 8; ++i) {
            const int lin = tid + i * 128;
            const int row = lin >> 4, ch = lin & 15;
            cp_async16(sb + QSM + row * 272 + ch * 16, g_qph + qb + row * 128 + ch * 8);
        }
    };
    auto issueK = [&](int kt) {
#pragma unroll
        for (int i = 0; i < 8; ++i) {
            const int lin = tid + i * 128;
            const int row = lin >> 4, ch = lin & 15;
            cp_async16(sb + KSM + row * 272 + ch * 16,
                       g_kph + (kvrow0 + kt * 64 + row) * 128 + ch * 8);
        }
    };
    auto issueV = [&](int kt) {
#pragma unroll
        for (int i = 0; i < 8; ++i) {
            const int lin = tid + i * 128;
            const int bf = lin >> 9, rem = lin & 511, row = rem >> 3, ch = rem & 7;
            cp_async16(sb + VSM(bf) + row * 144 + ch * 16,
                       (bf ? g_vih : g_vrh) + (kvrow0 + kt * 64 + row) * HD + ch * 8);
        }
    };

    float Or[8][4], Oi[8][4];
#pragma unroll
    for (int nb = 0; nb < 8; ++nb)
#pragma unroll
        for (int e = 0; e < 4; ++e) { Or[nb][e] = 0.f; Oi[nb][e] = 0.f; }
    float l0 = 0.f, l1 = 0.f;

    const uint32_t a_off = (uint32_t)((w * 16 + (L & 7) + (L & 8)) * 272 + ((L & 16) ? 16 : 0));
    const uint32_t brow4 = (uint32_t)((L & 7) * 272 + ((L & 8) ? 16 : 0) +
                                      ((L & 16) ? 2176 : 0));
    const uint32_t vrow4 = (uint32_t)(((L & 7) + (L & 8)) * 144 + ((L & 16) ? 16 : 0));

    issueQ(); issueK(0); CP_COMMIT();
    issueV(0); CP_COMMIT();

    for (int j = 0; j < NT; ++j) {
        CP_WAIT1();
        __syncthreads();

        float Sr[8][4], Si[8][4];
#pragma unroll
        for (int nb = 0; nb < 8; ++nb)
#pragma unroll
            for (int e = 0; e < 4; ++e) { Sr[nb][e] = 0.f; Si[nb][e] = 0.f; }

#pragma unroll
        for (int c = 0; c < 4; ++c) {
            uint32_t fh[4], gh[4], nh[4];
            ldsm_x4(fh, sb + QSM + a_off + c * 32);
            ldsm_x4(gh, sb + QSM + a_off + (c + 4) * 32);
#pragma unroll
            for (int r = 0; r < 4; ++r) nh[r] = fh[r] ^ 0x80008000u;
#pragma unroll
            for (int nb = 0; nb < 8; nb += 2) {
                const uint32_t ba = sb + KSM + (uint32_t)nb * 2176u + brow4;
                uint32_t bc[4], bd[4];
                ldsm_x4(bc, ba + c * 32);
                ldsm_x4(bd, ba + (c + 4) * 32);
                mma_f16(Sr[nb],     fh, bc);     mma_f16(Si[nb],     gh, bc);
                mma_f16(Sr[nb],     gh, bd);     mma_f16(Si[nb],     nh, bd);
                mma_f16(Sr[nb + 1], fh, bc + 2); mma_f16(Si[nb + 1], gh, bc + 2);
                mma_f16(Sr[nb + 1], gh, bd + 2); mma_f16(Si[nb + 1], nh, bd + 2);
            }
        }
        __syncthreads();

        if (j + 1 < NT) { issueK(j + 1); CP_COMMIT(); }

#pragma unroll
        for (int nb = 0; nb < 8; ++nb)
#pragma unroll
            for (int e = 0; e < 4; ++e) {
                const float x = fmaf(Sr[nb][e], Sr[nb][e], Si[nb][e] * Si[nb][e]);
                float rs; asm("rsqrt.approx.f32 %0, %1;" : "=f"(rs) : "f"(x + 1e-30f));
                const float p = ex2f((EXP_C * x) * rs - PBIAS);
                Sr[nb][e] = p;
                if (e < 2) l0 += p; else l1 += p;
            }

        uint32_t Pf[4][4];
#pragma unroll
        for (int kc = 0; kc < 4; ++kc) {
            Pf[kc][0] = packh(Sr[2 * kc][0],     Sr[2 * kc][1]);
            Pf[kc][1] = packh(Sr[2 * kc][2],     Sr[2 * kc][3]);
            Pf[kc][2] = packh(Sr[2 * kc + 1][0], Sr[2 * kc + 1][1]);
            Pf[kc][3] = packh(Sr[2 * kc + 1][2], Sr[2 * kc + 1][3]);
        }

        if (j + 1 < NT) { CP_WAIT1(); } else { CP_WAIT0(); }
        __syncthreads();

#pragma unroll
        for (int kc = 0; kc < 4; ++kc) {
            const uint32_t va = vrow4 + (uint32_t)kc * 2304u;
#pragma unroll
            for (int nb = 0; nb < 8; nb += 2) {
                uint32_t vr4[4], vi4[4];
                ldsm_x4t(vr4, sb + VSM(0) + va + nb * 16);
                ldsm_x4t(vi4, sb + VSM(1) + va + nb * 16);
                mma_f16(Or[nb],     Pf[kc], vr4);     mma_f16(Oi[nb],     Pf[kc], vi4);
                mma_f16(Or[nb + 1], Pf[kc], vr4 + 2); mma_f16(Oi[nb + 1], Pf[kc], vi4 + 2);
            }
        }
        __syncthreads();

        if (j + 1 < NT) { issueV(j + 1); CP_COMMIT(); }
    }

    l0 += __shfl_xor_sync(0xffffffffu, l0, 1);
    l0 += __shfl_xor_sync(0xffffffffu, l0, 2);
    l1 += __shfl_xor_sync(0xffffffffu, l1, 1);
    l1 += __shfl_xor_sync(0xffffffffu, l1, 2);
    const float inv0 = 1.f / l0, inv1 = 1.f / l1;
    const int b  = bh >> 4;
    const int hh = bh & 15;
    const int r0 = qt * 64 + w * 16 + (L >> 2);
    const size_t base0 = ((size_t)b * SEQ + r0) * DIM + hh * 64;
    const size_t base1 = base0 + (size_t)8 * DIM;
#pragma unroll
    for (int nb = 0; nb < 8; ++nb) {
        const int col = nb * 8 + 2 * (L & 3);
        *(uint32_t*)&g_oarh[base0 + col] = packh(Or[nb][0] * inv0, Or[nb][1] * inv0);
        *(uint32_t*)&g_oaih[base0 + col] = packh(Oi[nb][0] * inv0, Oi[nb][1] * inv0);
        *(uint32_t*)&g_oarh[base1 + col] = packh(Or[nb][2] * inv1, Or[nb][3] * inv1);
        *(uint32_t*)&g_oaih[base1 + col] = packh(Oi[nb][2] * inv1, Oi[nb][3] * inv1);
    }
}

// ============================================================
extern "C" void kernel_launch(void* const* d_in, const int* in_sizes, int n_in,
                              void* d_out, int out_size)
{
    const float* x_r    = (const float*)d_in[0];
    const float* x_i    = (const float*)d_in[1];
    const float* Wqkv_r = (const float*)d_in[2];
    const float* bqkv_r = (const float*)d_in[3];
    const float* Wqkv_i = (const float*)d_in[4];
    const float* bqkv_i = (const float*)d_in[5];
    const float* Wout_r = (const float*)d_in[6];
    const float* bout_r = (const float*)d_in[7];
    const float* Wout_i = (const float*)d_in[8];
    const float* bout_i = (const float*)d_in[9];

    cudaFuncSetAttribute(gemm_f16<1>, cudaFuncAttributeMaxDynamicSharedMemorySize, GEMM_SMEM);
    cudaFuncSetAttribute(gemm_f16<0>, cudaFuncAttributeMaxDynamicSharedMemorySize, GEMM_SMEM);
    cudaFuncSetAttribute(attn_mma,    cudaFuncAttributeMaxDynamicSharedMemorySize, ATT_SMEM);

    // 1) fused conversions
    split_all<<<2048, 256>>>(x_r, x_i, Wqkv_r, Wqkv_i, Wout_r, Wout_i);

    // 2) QKV projections (real + imag in one launch)
    dim3 gq(QKV_N / 128, M_TOTAL / 128, 2);    // (24, 32, 2)
    gemm_f16<1><<<gq, 128, GEMM_SMEM>>>(bqkv_r, bqkv_i, nullptr, nullptr);

    // 3) HMMA flash complex attention
    dim3 ga(SEQ / 64, BH);                     // (32, 32)
    attn_mma<<<ga, 128, ATT_SMEM>>>();

    // 4) output projections (real + imag in one launch)
    float* outr = (float*)d_out;
    float* outi = outr + (size_t)OUT_ELEMS;
    dim3 go(DIM / 128, M_TOTAL / 128, 2);      // (8, 32, 2)
    gemm_f16<0><<<go, 128, GEMM_SMEM>>>(bout_r, bout_i, outr, outi);
}

// round 17
// speedup vs baseline: 1.0299x; 1.0299x over previous
#include <cuda_runtime.h>
#include <cuda_fp16.h>
#include <cstdint>
#include <math.h>

#define B_SZ   2
#define SEQ    2048
#define DIM    1024
#define HEADS  16
#define HD     64
#define SCALE  0.125f
#define EXP_C  0.1803368801111243f   /* SCALE * log2(e) */
#define PBIAS  4.0f
#define M_TOTAL (B_SZ * SEQ)
#define QKV_N   (3 * DIM)
#define OUT_ELEMS  (B_SZ * SEQ * DIM)
#define BH      (B_SZ * HEADS)
#define PACKED_ELEMS (BH * SEQ * 128)
#define V_ELEMS      (BH * SEQ * HD)

// ---------------- scratch (static device globals, fp16, all plain) ----------------
__device__ __half g_xrh[OUT_ELEMS], g_xih[OUT_ELEMS];                  // x
__device__ __half g_wqr[QKV_N * DIM], g_wqi[QKV_N * DIM];              // Wqkv
__device__ __half g_wor[DIM * DIM], g_woi[DIM * DIM];                  // Wout
__device__ __half g_qph[PACKED_ELEMS];                                 // Q packed
__device__ __half g_kph[PACKED_ELEMS];                                 // K packed
__device__ __half g_vrh[V_ELEMS], g_vih[V_ELEMS];                      // V
__device__ __half g_oarh[OUT_ELEMS], g_oaih[OUT_ELEMS];                // O

// ---------------- helpers ----------------
__device__ __forceinline__ uint32_t smem_u32(const void* p) {
    uint32_t a;
    asm("{ .reg .u64 t; cvta.to.shared.u64 t, %1; cvt.u32.u64 %0, t; }" : "=r"(a) : "l"(p));
    return a;
}
__device__ __forceinline__ void cp_async16(uint32_t dst, const void* src) {
    asm volatile("cp.async.cg.shared.global [%0], [%1], 16;" :: "r"(dst), "l"(src) : "memory");
}
#define CP_COMMIT()  asm volatile("cp.async.commit_group;" ::: "memory")
#define CP_WAIT0()   asm volatile("cp.async.wait_group 0;" ::: "memory")
#define CP_WAIT1()   asm volatile("cp.async.wait_group 1;" ::: "memory")

__device__ __forceinline__ void mma_f16(float c[4], const uint32_t a[4], const uint32_t b[2]) {
    asm("mma.sync.aligned.m16n8k16.row.col.f32.f16.f16.f32 "
        "{%0,%1,%2,%3}, {%4,%5,%6,%7}, {%8,%9}, {%0,%1,%2,%3};"
        : "+f"(c[0]), "+f"(c[1]), "+f"(c[2]), "+f"(c[3])
        : "r"(a[0]), "r"(a[1]), "r"(a[2]), "r"(a[3]), "r"(b[0]), "r"(b[1]));
}
__device__ __forceinline__ void ldsm_x4(uint32_t r[4], uint32_t a) {
    asm volatile("ldmatrix.sync.aligned.m8n8.x4.shared.b16 {%0,%1,%2,%3}, [%4];"
                 : "=r"(r[0]), "=r"(r[1]), "=r"(r[2]), "=r"(r[3]) : "r"(a));
}
__device__ __forceinline__ void ldsm_x4t(uint32_t r[4], uint32_t a) {
    asm volatile("ldmatrix.sync.aligned.m8n8.x4.trans.shared.b16 {%0,%1,%2,%3}, [%4];"
                 : "=r"(r[0]), "=r"(r[1]), "=r"(r[2]), "=r"(r[3]) : "r"(a));
}
__device__ __forceinline__ uint32_t packh(float a, float b) {
    __half2 h = __floats2half2_rn(a, b);
    return *reinterpret_cast<uint32_t*>(&h);
}
__device__ __forceinline__ float ex2f(float x) {
    float r; asm("ex2.approx.f32 %0, %1;" : "=f"(r) : "f"(x)); return r;
}

// ---------------- fused fp32 -> fp16 conversions (region-per-block) ----------------
// region sizes in float4 units: x 512 blk each, wq 384 blk each, wo 128 blk each
__global__ void split_all(const float* __restrict__ x_r, const float* __restrict__ x_i,
                          const float* __restrict__ wq_r, const float* __restrict__ wq_i,
                          const float* __restrict__ wo_r, const float* __restrict__ wo_i)
{
    const int b = blockIdx.x;              // 2048 blocks, 2048 float4 each
    const float* src; __half* dst; int base4;
    if (b < 512)       { src = x_r;  dst = g_xrh; base4 = b * 2048; }
    else if (b < 1024) { src = x_i;  dst = g_xih; base4 = (b - 512)  * 2048; }
    else if (b < 1408) { src = wq_r; dst = g_wqr; base4 = (b - 1024) * 2048; }
    else if (b < 1792) { src = wq_i; dst = g_wqi; base4 = (b - 1408) * 2048; }
    else if (b < 1920) { src = wo_r; dst = g_wor; base4 = (b - 1792) * 2048; }
    else               { src = wo_i; dst = g_woi; base4 = (b - 1920) * 2048; }
#pragma unroll
    for (int it = 0; it < 8; ++it) {
        const int off = base4 + it * 256 + threadIdx.x;
        float4 v = ((const float4*)src)[off];
        uint2 hp;
        hp.x = packh(v.x, v.y); hp.y = packh(v.z, v.w);
        ((uint2*)dst)[off] = hp;
    }
}

// ============================================================
// HMMA plain-fp16 GEMM (R15 proven config): D = A @ B^T + bias.
// 256 threads, 8 warps (2x4), warp tile 64x32, K-chunk 64,
// 2-stage cp.async, pitch 144 B, 2 CTA/SM.
// ============================================================
#define TILE_G 18432                   /* 128 rows x 144 B */
#define STG_B  (2 * TILE_G)            /* A, B             */
#define GEMM_SMEM (2 * STG_B)          /* 73728            */
#define NCHUNK 16

template<int QKV>
__global__ __launch_bounds__(256, 2)
void gemm_f16(const float* __restrict__ bias_r, const float* __restrict__ bias_i,
              float* __restrict__ Yr, float* __restrict__ Yi)
{
    extern __shared__ char smc[];
    const uint32_t sb = smem_u32(smc);
    const int tid = threadIdx.x;
    const int wid = tid >> 5, lid = tid & 31;
    const int wm = wid >> 2, wn = wid & 3;
    const int g = lid >> 2, tig = lid & 3;
    const int n0 = blockIdx.x * 128;
    const int m0 = blockIdx.y * 128;
    const int z  = blockIdx.z;

    const __half *A, *B;
    const float* bias;
    if (QKV) {
        if (z == 0) { A = g_xrh;  B = g_wqr; bias = bias_r; }
        else        { A = g_xih;  B = g_wqi; bias = bias_i; }
    } else {
        if (z == 0) { A = g_oarh; B = g_wor; bias = bias_r; }
        else        { A = g_oaih; B = g_woi; bias = bias_i; }
    }
    float* Y = (z == 0) ? Yr : Yi;

    auto issue_cp = [&](int chunk, int s) {
        const int k0 = chunk * 64;
        const uint32_t base = sb + (uint32_t)s * STG_B;
#pragma unroll
        for (int i = 0; i < 8; ++i) {
            const int lin = tid + i * 256;           // 0..2047
            const int t   = lin >> 10;               // 0=A, 1=B
            const int rc  = lin & 1023;
            const int row = rc >> 3, c = rc & 7;
            cp_async16(base + t * TILE_G + row * 144 + c * 16,
                       (t ? B : A) + (size_t)((t ? n0 : m0) + row) * DIM + k0 + c * 8);
        }
    };

    const uint32_t a_rel = (uint32_t)((wm * 64 + (lid & 15)) * 144 + ((lid >> 4) << 4));
    const uint32_t b_rel = (uint32_t)((wn * 32 + (lid & 7) + ((lid & 16) >> 1)) * 144 +
                                      ((lid & 8) << 1));

    float acc[4][4][4];
#pragma unroll
    for (int a = 0; a < 4; a++)
#pragma unroll
        for (int b = 0; b < 4; b++)
#pragma unroll
            for (int c = 0; c < 4; c++) acc[a][b][c] = 0.f;

    issue_cp(0, 0); CP_COMMIT();

    for (int j = 0; j < NCHUNK; ++j) {
        CP_WAIT0();
        __syncthreads();                 // chunk j visible; other stage free
        if (j + 1 < NCHUNK) { issue_cp(j + 1, (j + 1) & 1); CP_COMMIT(); }

        const uint32_t st = sb + (uint32_t)(j & 1) * STG_B;
        const uint32_t aA = st + a_rel;
        const uint32_t aB = st + TILE_G + b_rel;

#pragma unroll
        for (int ks = 0; ks < 4; ++ks) {
            uint32_t b01[4], b23[4];
            ldsm_x4(b01, aB + ks * 32);
            ldsm_x4(b23, aB + 16 * 144 + ks * 32);
#pragma unroll
            for (int mi = 0; mi < 4; ++mi) {
                uint32_t ah[4];
                ldsm_x4(ah, aA + mi * (16 * 144) + ks * 32);
                mma_f16(acc[mi][0], ah, b01);
                mma_f16(acc[mi][1], ah, b01 + 2);
                mma_f16(acc[mi][2], ah, b23);
                mma_f16(acc[mi][3], ah, b23 + 2);
            }
        }
    }

    // ---- epilogue ----
#pragma unroll
    for (int nb = 0; nb < 4; ++nb) {
        const int n = n0 + wn * 32 + nb * 8 + tig * 2;
        const float b0v = bias[n], b1v = bias[n + 1];
#pragma unroll
        for (int mi = 0; mi < 4; ++mi) {
            const int mlo = m0 + wm * 64 + mi * 16 + g;
#pragma unroll
            for (int half = 0; half < 2; ++half) {
                const int m = mlo + half * 8;
                const float y0 = acc[mi][nb][half * 2 + 0] + b0v;
                const float y1 = acc[mi][nb][half * 2 + 1] + b1v;
                if (!QKV) {
                    *(float2*)&Y[(size_t)m * DIM + n] = make_float2(y0, y1);
                } else {
                    const int which = n >> 10;
                    const int h = (n >> 6) & 15;
                    const int d = n & 63;
                    const int bh = (m >> 11) * HEADS + h;
                    const int ns = m & 2047;
                    const uint32_t hp = packh(y0, y1);
                    if (which == 2) {
                        const size_t idx = ((size_t)bh * SEQ + ns) * HD + d;
                        if (z == 0) *(uint32_t*)&g_vrh[idx] = hp;
                        else        *(uint32_t*)&g_vih[idx] = hp;
                    } else {
                        const size_t idx = ((size_t)bh * SEQ + ns) * 128 + d + (z ? 64 : 0);
                        if (which == 0) *(uint32_t*)&g_qph[idx] = hp;
                        else            *(uint32_t*)&g_kph[idx] = hp;
                    }
                }
            }
        }
    }
}

// ============================================================
// HMMA flash complex attention (unchanged from Round 15).
// ============================================================
#define NT 32
#define QSM   0u
#define KSM   17408u
#define VSM(b) (34816u + (uint32_t)(b) * 9216u)
#define ATT_SMEM 53248

__global__ __launch_bounds__(128, 2)
void attn_mma()
{
    extern __shared__ char smb[];
    const uint32_t sb = smem_u32(smb);
    const int tid = threadIdx.x, w = tid >> 5, L = tid & 31;
    const int bh = blockIdx.y, qt = blockIdx.x;
    const size_t kvrow0 = (size_t)bh * SEQ;

    auto issueQ = [&]() {
        const size_t qb = (kvrow0 + (size_t)qt * 64) * 128;
#pragma unroll
        for (int i = 0; i < 8; ++i) {
            const int lin = tid + i * 128;
            const int row = lin >> 4, ch = lin & 15;
            cp_async16(sb + QSM + row * 272 + ch * 16, g_qph + qb + row * 128 + ch * 8);
        }
    };
    auto issueK = [&](int kt) {
#pragma unroll
        for (int i = 0; i < 8; ++i) {
            const int lin = tid + i * 128;
            const int row = lin >> 4, ch = lin & 15;
            cp_async16(sb + KSM + row * 272 + ch * 16,
                       g_kph + (kvrow0 + kt * 64 + row) * 128 + ch * 8);
        }
    };
    auto issueV = [&](int kt) {
#pragma unroll
        for (int i = 0; i < 8; ++i) {
            const int lin = tid + i * 128;
            const int bf = lin >> 9, rem = lin & 511, row = rem >> 3, ch = rem & 7;
            cp_async16(sb + VSM(bf) + row * 144 + ch * 16,
                       (bf ? g_vih : g_vrh) + (kvrow0 + kt * 64 + row) * HD + ch * 8);
        }
    };

    float Or[8][4], Oi[8][4];
#pragma unroll
    for (int nb = 0; nb < 8; ++nb)
#pragma unroll
        for (int e = 0; e < 4; ++e) { Or[nb][e] = 0.f; Oi[nb][e] = 0.f; }
    float l0 = 0.f, l1 = 0.f;

    const uint32_t a_off = (uint32_t)((w * 16 + (L & 7) + (L & 8)) * 272 + ((L & 16) ? 16 : 0));
    const uint32_t brow4 = (uint32_t)((L & 7) * 272 + ((L & 8) ? 16 : 0) +
                                      ((L & 16) ? 2176 : 0));
    const uint32_t vrow4 = (uint32_t)(((L & 7) + (L & 8)) * 144 + ((L & 16) ? 16 : 0));

    issueQ(); issueK(0); CP_COMMIT();
    issueV(0); CP_COMMIT();

    for (int j = 0; j < NT; ++j) {
        CP_WAIT1();
        __syncthreads();

        float Sr[8][4], Si[8][4];
#pragma unroll
        for (int nb = 0; nb < 8; ++nb)
#pragma unroll
            for (int e = 0; e < 4; ++e) { Sr[nb][e] = 0.f; Si[nb][e] = 0.f; }

#pragma unroll
        for (int c = 0; c < 4; ++c) {
            uint32_t fh[4], gh[4], nh[4];
            ldsm_x4(fh, sb + QSM + a_off + c * 32);
            ldsm_x4(gh, sb + QSM + a_off + (c + 4) * 32);
#pragma unroll
            for (int r = 0; r < 4; ++r) nh[r] = fh[r] ^ 0x80008000u;
#pragma unroll
            for (int nb = 0; nb < 8; nb += 2) {
                const uint32_t ba = sb + KSM + (uint32_t)nb * 2176u + brow4;
                uint32_t bc[4], bd[4];
                ldsm_x4(bc, ba + c * 32);
                ldsm_x4(bd, ba + (c + 4) * 32);
                mma_f16(Sr[nb],     fh, bc);     mma_f16(Si[nb],     gh, bc);
                mma_f16(Sr[nb],     gh, bd);     mma_f16(Si[nb],     nh, bd);
                mma_f16(Sr[nb + 1], fh, bc + 2); mma_f16(Si[nb + 1], gh, bc + 2);
                mma_f16(Sr[nb + 1], gh, bd + 2); mma_f16(Si[nb + 1], nh, bd + 2);
            }
        }
        __syncthreads();

        if (j + 1 < NT) { issueK(j + 1); CP_COMMIT(); }

#pragma unroll
        for (int nb = 0; nb < 8; ++nb)
#pragma unroll
            for (int e = 0; e < 4; ++e) {
                const float x = fmaf(Sr[nb][e], Sr[nb][e], Si[nb][e] * Si[nb][e]);
                float rs; asm("rsqrt.approx.f32 %0, %1;" : "=f"(rs) : "f"(x + 1e-30f));
                const float p = ex2f((EXP_C * x) * rs - PBIAS);
                Sr[nb][e] = p;
                if (e < 2) l0 += p; else l1 += p;
            }

        uint32_t Pf[4][4];
#pragma unroll
        for (int kc = 0; kc < 4; ++kc) {
            Pf[kc][0] = packh(Sr[2 * kc][0],     Sr[2 * kc][1]);
            Pf[kc][1] = packh(Sr[2 * kc][2],     Sr[2 * kc][3]);
            Pf[kc][2] = packh(Sr[2 * kc + 1][0], Sr[2 * kc + 1][1]);
            Pf[kc][3] = packh(Sr[2 * kc + 1][2], Sr[2 * kc + 1][3]);
        }

        if (j + 1 < NT) { CP_WAIT1(); } else { CP_WAIT0(); }
        __syncthreads();

#pragma unroll
        for (int kc = 0; kc < 4; ++kc) {
            const uint32_t va = vrow4 + (uint32_t)kc * 2304u;
#pragma unroll
            for (int nb = 0; nb < 8; nb += 2) {
                uint32_t vr4[4], vi4[4];
                ldsm_x4t(vr4, sb + VSM(0) + va + nb * 16);
                ldsm_x4t(vi4, sb + VSM(1) + va + nb * 16);
                mma_f16(Or[nb],     Pf[kc], vr4);     mma_f16(Oi[nb],     Pf[kc], vi4);
                mma_f16(Or[nb + 1], Pf[kc], vr4 + 2); mma_f16(Oi[nb + 1], Pf[kc], vi4 + 2);
            }
        }
        __syncthreads();

        if (j + 1 < NT) { issueV(j + 1); CP_COMMIT(); }
    }

    l0 += __shfl_xor_sync(0xffffffffu, l0, 1);
    l0 += __shfl_xor_sync(0xffffffffu, l0, 2);
    l1 += __shfl_xor_sync(0xffffffffu, l1, 1);
    l1 += __shfl_xor_sync(0xffffffffu, l1, 2);
    const float inv0 = 1.f / l0, inv1 = 1.f / l1;
    const int b  = bh >> 4;
    const int hh = bh & 15;
    const int r0 = qt * 64 + w * 16 + (L >> 2);
    const size_t base0 = ((size_t)b * SEQ + r0) * DIM + hh * 64;
    const size_t base1 = base0 + (size_t)8 * DIM;
#pragma unroll
    for (int nb = 0; nb < 8; ++nb) {
        const int col = nb * 8 + 2 * (L & 3);
        *(uint32_t*)&g_oarh[base0 + col] = packh(Or[nb][0] * inv0, Or[nb][1] * inv0);
        *(uint32_t*)&g_oaih[base0 + col] = packh(Oi[nb][0] * inv0, Oi[nb][1] * inv0);
        *(uint32_t*)&g_oarh[base1 + col] = packh(Or[nb][2] * inv1, Or[nb][3] * inv1);
        *(uint32_t*)&g_oaih[base1 + col] = packh(Oi[nb][2] * inv1, Oi[nb][3] * inv1);
    }
}

// ============================================================
extern "C" void kernel_launch(void* const* d_in, const int* in_sizes, int n_in,
                              void* d_out, int out_size)
{
    const float* x_r    = (const float*)d_in[0];
    const float* x_i    = (const float*)d_in[1];
    const float* Wqkv_r = (const float*)d_in[2];
    const float* bqkv_r = (const float*)d_in[3];
    const float* Wqkv_i = (const float*)d_in[4];
    const float* bqkv_i = (const float*)d_in[5];
    const float* Wout_r = (const float*)d_in[6];
    const float* bout_r = (const float*)d_in[7];
    const float* Wout_i = (const float*)d_in[8];
    const float* bout_i = (const float*)d_in[9];

    cudaFuncSetAttribute(gemm_f16<1>, cudaFuncAttributeMaxDynamicSharedMemorySize, GEMM_SMEM);
    cudaFuncSetAttribute(gemm_f16<0>, cudaFuncAttributeMaxDynamicSharedMemorySize, GEMM_SMEM);
    cudaFuncSetAttribute(attn_mma,    cudaFuncAttributeMaxDynamicSharedMemorySize, ATT_SMEM);

    // 1) fused conversions (region-per-block)
    split_all<<<2048, 256>>>(x_r, x_i, Wqkv_r, Wqkv_i, Wout_r, Wout_i);

    // 2) QKV projections (real + imag in one launch)
    dim3 gq(QKV_N / 128, M_TOTAL / 128, 2);    // (24, 32, 2)
    gemm_f16<1><<<gq, 256, GEMM_SMEM>>>(bqkv_r, bqkv_i, nullptr, nullptr);

    // 3) HMMA flash complex attention
    dim3 ga(SEQ / 64, BH);                     // (32, 32)
    attn_mma<<<ga, 128, ATT_SMEM>>>();

    // 4) output projections (real + imag in one launch)
    float* outr = (float*)d_out;
    float* outi = outr + (size_t)OUT_ELEMS;
    dim3 go(DIM / 128, M_TOTAL / 128, 2);      // (8, 32, 2)
    gemm_f16<0><<<go, 256, GEMM_SMEM>>>(bout_r, bout_i, outr, outi);
}